// round 8
// baseline (speedup 1.0000x reference)
#include <cuda_runtime.h>
#include <cuda_fp16.h>
#include <cstdint>

// ---------------- problem constants ----------------
#define M_TOTAL   4096
#define K_TOTAL   4096
#define N_TOTAL   11008

#define BM        128
#define BN        128
#define BK        64                  // fp16 per K chunk (128 B/row)
#define NKIT      (K_TOTAL / BK)      // 64
#define MT_TILES  (M_TOTAL / BM)      // 32
#define NT_TILES  (N_TOTAL / BN)      // 86
#define NTILES    (MT_TILES * NT_TILES)  // 2752
#define STAGES    3
#define NTHREADS  256

#define A_STAGE_BYTES (BM * 128)                        // 16384
#define B_STAGE_BYTES (BN * 128)                        // 16384
#define STAGE_BYTES   (A_STAGE_BYTES + B_STAGE_BYTES)   // 32768
#define SMEM_BYTES    (STAGES * STAGE_BYTES)            // 98304 -> 2 CTAs/SM

// ---------------- device scratch ----------------
static __device__ __align__(16) __half g_xh[(size_t)M_TOTAL * K_TOTAL];   // ~34 MB
static __device__ __align__(16) __half g_w [(size_t)N_TOTAL * K_TOTAL];   // ~90 MB
static __device__ int g_ctr;

// ---------------- helpers ----------------
#define SWZ(off) ((off) ^ (((off) >> 3) & 0x70))

__device__ __forceinline__ uint32_t smem_u32(const void* p) {
    uint32_t a;
    asm("{ .reg .u64 t; cvta.to.shared.u64 t, %1; cvt.u32.u64 %0, t; }" : "=r"(a) : "l"(p));
    return a;
}

#define CP_ASYNC16(dst_u32, src_ptr) \
    asm volatile("cp.async.cg.shared.global [%0], [%1], 16;" :: "r"(dst_u32), "l"(src_ptr))
#define CP_COMMIT() asm volatile("cp.async.commit_group;" ::: "memory")
#define CP_WAIT1()  asm volatile("cp.async.wait_group 1;" ::: "memory")
#define CP_WAIT0()  asm volatile("cp.async.wait_group 0;" ::: "memory")

#define LDSM_X4(r0, r1, r2, r3, addr) \
    asm volatile("ldmatrix.sync.aligned.m8n8.x4.shared.b16 {%0,%1,%2,%3}, [%4];" \
                 : "=r"(r0), "=r"(r1), "=r"(r2), "=r"(r3) : "r"(addr))

#define MMA16816(c, a, b) \
    asm volatile("mma.sync.aligned.m16n8k16.row.col.f32.f16.f16.f32 " \
                 "{%0,%1,%2,%3}, {%4,%5,%6,%7}, {%8,%9}, {%0,%1,%2,%3};" \
                 : "+f"((c)[0]), "+f"((c)[1]), "+f"((c)[2]), "+f"((c)[3]) \
                 : "r"((a)[0]), "r"((a)[1]), "r"((a)[2]), "r"((a)[3]), \
                   "r"((b)[0]), "r"((b)[1]))

// ---------------- fused prep kernel ----------------
__device__ __forceinline__ uint32_t dq_pair(int v) {
    int lo = (v & 15) - 8;
    int hi = ((v >> 4) & 15) - 8;
    __half2 h = __floats2half2_rn((float)lo, (float)hi);
    return *(uint32_t*)&h;
}

__global__ void k_prep(const float* __restrict__ x, const int* __restrict__ wp) {
    if (blockIdx.x == 0 && threadIdx.x == 0) g_ctr = 0;   // reset persistent-tile counter
    if (blockIdx.x < 8192) {
        size_t i = ((size_t)blockIdx.x * blockDim.x + threadIdx.x) * 8;
        float4 a = *(const float4*)(x + i);
        float4 b = *(const float4*)(x + i + 4);
        __half2 h0 = __floats2half2_rn(a.x, a.y);
        __half2 h1 = __floats2half2_rn(a.z, a.w);
        __half2 h2 = __floats2half2_rn(b.x, b.y);
        __half2 h3 = __floats2half2_rn(b.z, b.w);
        uint4 o;
        o.x = *(uint32_t*)&h0; o.y = *(uint32_t*)&h1;
        o.z = *(uint32_t*)&h2; o.w = *(uint32_t*)&h3;
        *(uint4*)(g_xh + i) = o;
    } else {
        size_t i = ((size_t)(blockIdx.x - 8192) * blockDim.x + threadIdx.x) * 4;
        int4 v = *(const int4*)(wp + i);
        uint4 o;
        o.x = dq_pair(v.x); o.y = dq_pair(v.y);
        o.z = dq_pair(v.z); o.w = dq_pair(v.w);
        *(uint4*)(g_w + 2 * i) = o;
    }
}

// ---------------- persistent GEMM kernel ----------------
// 256 threads, 8 warps in 2(M) x 4(N), warp tile 64x32; 2 CTAs/SM
__global__ __launch_bounds__(NTHREADS, 2) void k_gemm(const float* __restrict__ scale,
                                                      const float* __restrict__ bias,
                                                      float* __restrict__ out) {
    extern __shared__ __align__(1024) char smem[];
    __shared__ int s_tile;

    const int tid  = threadIdx.x;
    const int wid  = tid >> 5;
    const int lane = tid & 31;

    const int wm0 = (wid & 1) * 64;       // warp M offset
    const int wn0 = (wid >> 1) * 32;      // warp N offset

    const uint32_t sb = smem_u32(smem);
    const int ac8  = tid & 7;
    const int lrow = lane & 15;
    const int lchk = lane >> 4;

    // ---- loop-invariant per-thread constants ----
    // cp.async: 4 A-chunks + 4 B-chunks per thread per stage
    uint32_t dA[4], dB[4];                 // smem dst offsets within a stage
    uint32_t oBy[4];                       // gmem BYTE offsets (same pattern A and B)
    #pragma unroll
    for (int t = 0; t < 4; ++t) {
        int row = (tid + t * NTHREADS) >> 3;
        dA[t] = SWZ(row * 128 + ac8 * 16);
        dB[t] = A_STAGE_BYTES + dA[t];
        oBy[t] = ((uint32_t)row * K_TOTAL + ac8 * 8) * 2;
    }
    // LDSM swizzle algebra: row&7 == lrow&7 for every fragment row.
    // addr = stage_base + baseF + kterm[ks], with
    //   baseF   = row*128 + ((lchk ^ (lrow&1)) << 4)        (per fragment)
    //   kterm   = ((2*ks) ^ (lrow&6)) << 4                  (per ks, frag-independent)
    const uint32_t b0x = ((uint32_t)(lchk ^ (lrow & 1))) << 4;
    uint32_t baseA[4], baseB[2];
    #pragma unroll
    for (int mti = 0; mti < 4; ++mti)
        baseA[mti] = (uint32_t)(wm0 + mti * 16 + lrow) * 128 + b0x;
    #pragma unroll
    for (int np = 0; np < 2; ++np)
        baseB[np] = A_STAGE_BYTES + (uint32_t)(wn0 + np * 16 + lrow) * 128 + b0x;
    const uint32_t kx6 = (uint32_t)(lrow & 6);

    for (;;) {
        if (tid == 0) s_tile = atomicAdd(&g_ctr, 1);
        __syncthreads();
        const int t = s_tile;
        if (t >= NTILES) break;

        const int mt = t % MT_TILES;      // mt fastest -> B tile L2-shared across wave
        const int nt = t / MT_TILES;
        const int m0 = mt * BM;
        const int n0 = nt * BN;

        float acc[4][4][4];
        #pragma unroll
        for (int i = 0; i < 4; ++i)
            #pragma unroll
            for (int j = 0; j < 4; ++j)
                #pragma unroll
                for (int k = 0; k < 4; ++k) acc[i][j][k] = 0.f;

        // per-tile gmem base pointers, advanced 128 B per stage
        const char* gAp = (const char*)(g_xh + (size_t)m0 * K_TOTAL);
        const char* gBp = (const char*)(g_w  + (size_t)n0 * K_TOTAL);

        auto load_stage = [&](int s) {
            const uint32_t base = sb + s * STAGE_BYTES;
            #pragma unroll
            for (int tt = 0; tt < 4; ++tt)
                CP_ASYNC16(base + dA[tt], gAp + oBy[tt]);
            #pragma unroll
            for (int tt = 0; tt < 4; ++tt)
                CP_ASYNC16(base + dB[tt], gBp + oBy[tt]);
            gAp += BK * 2;
            gBp += BK * 2;
        };

        load_stage(0); CP_COMMIT();
        load_stage(1); CP_COMMIT();

        int sidx = 0;
        int sld  = 2;
        for (int it = 0; it < NKIT; ++it) {
            CP_WAIT1();
            __syncthreads();
            if (it + 2 < NKIT) {
                load_stage(sld);
                if (++sld == STAGES) sld = 0;
            }
            CP_COMMIT();

            const uint32_t sA = sb + sidx * STAGE_BYTES;

            #pragma unroll
            for (int ks = 0; ks < 4; ++ks) {
                const uint32_t kbase = sA + ((((uint32_t)(2 * ks)) ^ kx6) << 4);
                uint32_t a[4][4];
                #pragma unroll
                for (int mti = 0; mti < 4; ++mti)
                    LDSM_X4(a[mti][0], a[mti][1], a[mti][2], a[mti][3],
                            kbase + baseA[mti]);
                uint32_t b[4][2];
                #pragma unroll
                for (int np = 0; np < 2; ++np) {
                    uint32_t r0, r1, r2, r3;
                    LDSM_X4(r0, r1, r2, r3, kbase + baseB[np]);
                    b[2 * np + 0][0] = r0; b[2 * np + 0][1] = r2;
                    b[2 * np + 1][0] = r1; b[2 * np + 1][1] = r3;
                }
                #pragma unroll
                for (int mti = 0; mti < 4; ++mti)
                    #pragma unroll
                    for (int nti = 0; nti < 4; ++nti)
                        MMA16816(acc[mti][nti], a[mti], b[nti]);
            }
            if (++sidx == STAGES) sidx = 0;
        }
        CP_WAIT0();

        // ---------------- epilogue ----------------
        {
            const int row_base = m0 + wm0;
            const int col_base = n0 + wn0;
            const int r_in = lane >> 2;
            const int c_in = (lane & 3) * 2;

            #pragma unroll
            for (int nti = 0; nti < 4; ++nti) {
                const int c = col_base + nti * 8 + c_in;
                const float2 sc = *(const float2*)(scale + c);
                const float2 bi = *(const float2*)(bias + c);
                #pragma unroll
                for (int mti = 0; mti < 4; ++mti) {
                    const int r0 = row_base + mti * 16 + r_in;
                    float2 v0, v1;
                    v0.x = acc[mti][nti][0] * sc.x + bi.x;
                    v0.y = acc[mti][nti][1] * sc.y + bi.y;
                    v1.x = acc[mti][nti][2] * sc.x + bi.x;
                    v1.y = acc[mti][nti][3] * sc.y + bi.y;
                    *(float2*)(out + (size_t)r0 * N_TOTAL + c)       = v0;
                    *(float2*)(out + (size_t)(r0 + 8) * N_TOTAL + c) = v1;
                }
            }
        }
    }
}

// ---------------- launch ----------------
extern "C" void kernel_launch(void* const* d_in, const int* in_sizes, int n_in,
                              void* d_out, int out_size) {
    const float* x   = (const float*)d_in[0];
    const int*   wp  = (const int*)d_in[1];
    const float* scl = (const float*)d_in[2];
    const float* bia = (const float*)d_in[3];
    float* out = (float*)d_out;

    cudaFuncSetAttribute(k_gemm, cudaFuncAttributeMaxDynamicSharedMemorySize, SMEM_BYTES);

    // fused prep: 8192 convert blocks + 22016 dequant blocks
    k_prep<<<30208, 256>>>(x, wp);
    // persistent GEMM, 2 CTAs/SM
    k_gemm<<<296, NTHREADS, SMEM_BYTES>>>(scl, bia, out);
}

// round 9
// speedup vs baseline: 1.0569x; 1.0569x over previous
#include <cuda_runtime.h>
#include <cuda_fp16.h>
#include <cstdint>

// ---------------- problem constants ----------------
#define M_TOTAL   4096
#define K_TOTAL   4096
#define N_TOTAL   11008

#define BM        128
#define BN        128
#define BK        64                  // fp16 per K chunk (128 B/row)
#define NKIT      (K_TOTAL / BK)      // 64
#define MT_TILES  (M_TOTAL / BM)      // 32
#define NT_TILES  (N_TOTAL / BN)      // 86
#define NTILES    (MT_TILES * NT_TILES)  // 2752
#define STAGES    3
#define NTHREADS  256

#define CHUNK_BYTES   16384                             // one (tile,kc) block, pre-swizzled
#define A_STAGE_BYTES CHUNK_BYTES
#define STAGE_BYTES   (2 * CHUNK_BYTES)                 // A + B = 32768
#define SMEM_DATA     (STAGES * STAGE_BYTES)            // 98304
#define SMEM_MBAR     SMEM_DATA                         // 3 x 8B mbarriers
#define SMEM_BYTES    (SMEM_DATA + 64)

// ---------------- device scratch (tile-major, pre-swizzled) ----------------
// layout: chunk (t, kc) at byte offset (t*NKIT + kc) * 16384; within chunk:
// SWZ(row_in_tile*128 + (k_in_chunk/8)*16) holds 8 fp16 (16B)
static __device__ __align__(16) __half g_xh[(size_t)M_TOTAL * K_TOTAL];   // ~34 MB
static __device__ __align__(16) __half g_w [(size_t)N_TOTAL * K_TOTAL];   // ~90 MB
static __device__ int g_ctr;

// ---------------- helpers ----------------
#define SWZ(off) ((off) ^ (((off) >> 3) & 0x70))

__device__ __forceinline__ uint32_t smem_u32(const void* p) {
    uint32_t a;
    asm("{ .reg .u64 t; cvta.to.shared.u64 t, %1; cvt.u32.u64 %0, t; }" : "=r"(a) : "l"(p));
    return a;
}

#define CP_BULK(dst_u32, src_ptr, bytes, mbar_u32) \
    asm volatile("cp.async.bulk.shared::cluster.global.mbarrier::complete_tx::bytes " \
                 "[%0], [%1], %2, [%3];" \
                 :: "r"(dst_u32), "l"(src_ptr), "r"(bytes), "r"(mbar_u32) : "memory")

#define MBARRIER_INIT(mbar, cnt) \
    asm volatile("mbarrier.init.shared.b64 [%0], %1;" \
                 :: "r"((uint32_t)(mbar)), "r"((uint32_t)(cnt)) : "memory")
#define MBARRIER_INVAL(mbar) \
    asm volatile("mbarrier.inval.shared.b64 [%0];" :: "r"((uint32_t)(mbar)) : "memory")
#define MBARRIER_EXPECT_TX(mbar, tx) \
    asm volatile("mbarrier.arrive.expect_tx.shared.b64 _, [%0], %1;" \
                 :: "r"((uint32_t)(mbar)), "r"((uint32_t)(tx)) : "memory")

#define MBARRIER_WAIT_PARITY(mbar_smem_addr, phase_parity) do { \
    uint32_t _mbar = (uint32_t)(mbar_smem_addr); \
    uint32_t _parity = (uint32_t)(phase_parity); \
    uint32_t _done; \
    asm volatile( \
        "{\n\t.reg .pred p;\n\t" \
        "mbarrier.try_wait.parity.acquire.cta.shared::cta.b64 p, [%1], %2;\n\t" \
        "selp.b32 %0, 1, 0, p;\n\t}" \
        : "=r"(_done) : "r"(_mbar), "r"(_parity) : "memory"); \
    if (!_done) { \
        asm volatile( \
            "{\n\t.reg .pred P1;\n\t" \
            "WAIT_LOOP_%=:\n\t" \
            "mbarrier.try_wait.parity.acquire.cta.shared::cta.b64 P1, [%0], %1, 0x989680;\n\t" \
            "@P1 bra.uni WAIT_DONE_%=;\n\t" \
            "bra.uni WAIT_LOOP_%=;\n\t" \
            "WAIT_DONE_%=:\n\t}" \
            :: "r"(_mbar), "r"(_parity) : "memory"); \
    } \
} while (0)

#define LDSM_X4(r0, r1, r2, r3, addr) \
    asm volatile("ldmatrix.sync.aligned.m8n8.x4.shared.b16 {%0,%1,%2,%3}, [%4];" \
                 : "=r"(r0), "=r"(r1), "=r"(r2), "=r"(r3) : "r"(addr))

#define MMA16816(c, a, b) \
    asm volatile("mma.sync.aligned.m16n8k16.row.col.f32.f16.f16.f32 " \
                 "{%0,%1,%2,%3}, {%4,%5,%6,%7}, {%8,%9}, {%0,%1,%2,%3};" \
                 : "+f"((c)[0]), "+f"((c)[1]), "+f"((c)[2]), "+f"((c)[3]) \
                 : "r"((a)[0]), "r"((a)[1]), "r"((a)[2]), "r"((a)[3]), \
                   "r"((b)[0]), "r"((b)[1]))

// ---------------- fused prep kernel: tile-major pre-swizzled outputs ----------------
__device__ __forceinline__ uint32_t dq_pair(int v) {
    int lo = (v & 15) - 8;
    int hi = ((v >> 4) & 15) - 8;
    __half2 h = __floats2half2_rn((float)lo, (float)hi);
    return *(uint32_t*)&h;
}

__global__ void k_prep(const float* __restrict__ x, const int* __restrict__ wp) {
    if (blockIdx.x == 0 && threadIdx.x == 0) g_ctr = 0;   // reset persistent-tile counter
    if (blockIdx.x < 8192) {
        // x: 8 consecutive floats -> one 16B chunk in tiled layout
        size_t i = ((size_t)blockIdx.x * blockDim.x + threadIdx.x) * 8;
        int m = (int)(i >> 12);           // / 4096
        int k = (int)(i & 4095);
        float4 a = *(const float4*)(x + i);
        float4 b = *(const float4*)(x + i + 4);
        __half2 h0 = __floats2half2_rn(a.x, a.y);
        __half2 h1 = __floats2half2_rn(a.z, a.w);
        __half2 h2 = __floats2half2_rn(b.x, b.y);
        __half2 h3 = __floats2half2_rn(b.z, b.w);
        uint4 o;
        o.x = *(uint32_t*)&h0; o.y = *(uint32_t*)&h1;
        o.z = *(uint32_t*)&h2; o.w = *(uint32_t*)&h3;
        int chunk = (m >> 7) * NKIT + (k >> 6);
        uint32_t off = SWZ((uint32_t)(m & 127) * 128 + (uint32_t)((k & 63) >> 3) * 16);
        *(uint4*)((char*)g_xh + ((size_t)chunk << 14) + off) = o;
    } else {
        // W: 4 consecutive int32 -> 8 fp16 (k0..k0+7) -> one 16B chunk
        size_t c = ((size_t)(blockIdx.x - 8192) * blockDim.x + threadIdx.x) * 4;
        int o_row = (int)(c >> 11);       // / 2048 packed cols
        int k0 = (int)(c & 2047) * 2;
        int4 v = *(const int4*)(wp + c);
        uint4 o;
        o.x = dq_pair(v.x); o.y = dq_pair(v.y);
        o.z = dq_pair(v.z); o.w = dq_pair(v.w);
        int chunk = (o_row >> 7) * NKIT + (k0 >> 6);
        uint32_t off = SWZ((uint32_t)(o_row & 127) * 128 + (uint32_t)((k0 & 63) >> 3) * 16);
        *(uint4*)((char*)g_w + ((size_t)chunk << 14) + off) = o;
    }
}

// ---------------- persistent GEMM kernel ----------------
// 256 threads, 8 warps in 2(M) x 4(N), warp tile 64x32; 2 CTAs/SM; bulk-TMA loads
__global__ __launch_bounds__(NTHREADS, 2) void k_gemm(const float* __restrict__ scale,
                                                      const float* __restrict__ bias,
                                                      float* __restrict__ out) {
    extern __shared__ __align__(1024) char smem[];
    __shared__ int s_tile;

    const int tid  = threadIdx.x;
    const int wid  = tid >> 5;
    const int lane = tid & 31;

    const int wm0 = (wid & 1) * 64;       // warp M offset
    const int wn0 = (wid >> 1) * 32;      // warp N offset

    const uint32_t sb = smem_u32(smem);
    const uint32_t mb = sb + SMEM_MBAR;   // mbar[s] at mb + 8*s
    const int lrow = lane & 15;
    const int lchk = lane >> 4;

    // LDSM address algebra (row&7 == lrow&7 for all fragment rows)
    const uint32_t b0x = ((uint32_t)(lchk ^ (lrow & 1))) << 4;
    uint32_t baseA[4], baseB[2];
    #pragma unroll
    for (int mti = 0; mti < 4; ++mti)
        baseA[mti] = (uint32_t)(wm0 + mti * 16 + lrow) * 128 + b0x;
    #pragma unroll
    for (int np = 0; np < 2; ++np)
        baseB[np] = A_STAGE_BYTES + (uint32_t)(wn0 + np * 16 + lrow) * 128 + b0x;
    const uint32_t kx6 = (uint32_t)(lrow & 6);

    bool binit = false;

    for (;;) {
        if (tid == 0) s_tile = atomicAdd(&g_ctr, 1);
        __syncthreads();                  // also: all waits of prev tile done before re-init
        const int t = s_tile;
        if (t >= NTILES) break;

        const int mt = t % MT_TILES;      // mt fastest -> B tile L2-shared across wave
        const int nt = t / MT_TILES;
        const int m0 = mt * BM;
        const int n0 = nt * BN;

        if (tid == 0) {
            if (binit) {
                MBARRIER_INVAL(mb + 0); MBARRIER_INVAL(mb + 8); MBARRIER_INVAL(mb + 16);
            }
            MBARRIER_INIT(mb + 0, 1); MBARRIER_INIT(mb + 8, 1); MBARRIER_INIT(mb + 16, 1);
        }
        binit = true;
        __syncthreads();                  // init visible before any wait

        float acc[4][4][4];
        #pragma unroll
        for (int i = 0; i < 4; ++i)
            #pragma unroll
            for (int j = 0; j < 4; ++j)
                #pragma unroll
                for (int k = 0; k < 4; ++k) acc[i][j][k] = 0.f;

        // chunk base pointers for this tile (advance 16KB per stage)
        const char* gAp = (const char*)g_xh + ((size_t)(mt * NKIT) << 14);
        const char* gBp = (const char*)g_w  + ((size_t)(nt * NKIT) << 14);

        // prologue: stages 0,1
        if (tid == 0) {
            #pragma unroll
            for (int s = 0; s < 2; ++s) {
                const uint32_t bar = mb + 8 * s;
                MBARRIER_EXPECT_TX(bar, STAGE_BYTES);
                CP_BULK(sb + s * STAGE_BYTES,                 gAp + (size_t)s * CHUNK_BYTES, CHUNK_BYTES, bar);
                CP_BULK(sb + s * STAGE_BYTES + A_STAGE_BYTES, gBp + (size_t)s * CHUNK_BYTES, CHUNK_BYTES, bar);
            }
        }

        int sidx = 0;                     // stage of iter it (it % 3)
        int sld  = 2;                     // stage for iter it+2
        for (int it = 0; it < NKIT; ++it) {
            // issue it+2 (WAR-safe: barrier at end of it-1 already passed)
            if (tid == 0 && it + 2 < NKIT) {
                const uint32_t bar = mb + 8 * sld;
                MBARRIER_EXPECT_TX(bar, STAGE_BYTES);
                CP_BULK(sb + sld * STAGE_BYTES,                 gAp + ((size_t)(it + 2) << 14), CHUNK_BYTES, bar);
                CP_BULK(sb + sld * STAGE_BYTES + A_STAGE_BYTES, gBp + ((size_t)(it + 2) << 14), CHUNK_BYTES, bar);
            }

            MBARRIER_WAIT_PARITY(mb + 8 * sidx, (uint32_t)((it / 3) & 1));

            const uint32_t sA = sb + sidx * STAGE_BYTES;
            #pragma unroll
            for (int ks = 0; ks < 4; ++ks) {
                const uint32_t kbase = sA + ((((uint32_t)(2 * ks)) ^ kx6) << 4);
                uint32_t a[4][4];
                #pragma unroll
                for (int mti = 0; mti < 4; ++mti)
                    LDSM_X4(a[mti][0], a[mti][1], a[mti][2], a[mti][3],
                            kbase + baseA[mti]);
                uint32_t b[4][2];
                #pragma unroll
                for (int np = 0; np < 2; ++np) {
                    uint32_t r0, r1, r2, r3;
                    LDSM_X4(r0, r1, r2, r3, kbase + baseB[np]);
                    b[2 * np + 0][0] = r0; b[2 * np + 0][1] = r2;
                    b[2 * np + 1][0] = r1; b[2 * np + 1][1] = r3;
                }
                #pragma unroll
                for (int mti = 0; mti < 4; ++mti)
                    #pragma unroll
                    for (int nti = 0; nti < 4; ++nti)
                        MMA16816(acc[mti][nti], a[mti], b[nti]);
            }
            __syncthreads();              // all warps done with stage (it+2)%3's old data
            if (++sidx == STAGES) sidx = 0;
            if (++sld  == STAGES) sld  = 0;
        }

        // ---------------- epilogue ----------------
        {
            const int row_base = m0 + wm0;
            const int col_base = n0 + wn0;
            const int r_in = lane >> 2;
            const int c_in = (lane & 3) * 2;

            #pragma unroll
            for (int nti = 0; nti < 4; ++nti) {
                const int c = col_base + nti * 8 + c_in;
                const float2 sc = *(const float2*)(scale + c);
                const float2 bi = *(const float2*)(bias + c);
                #pragma unroll
                for (int mti = 0; mti < 4; ++mti) {
                    const int r0 = row_base + mti * 16 + r_in;
                    float2 v0, v1;
                    v0.x = acc[mti][nti][0] * sc.x + bi.x;
                    v0.y = acc[mti][nti][1] * sc.y + bi.y;
                    v1.x = acc[mti][nti][2] * sc.x + bi.x;
                    v1.y = acc[mti][nti][3] * sc.y + bi.y;
                    *(float2*)(out + (size_t)r0 * N_TOTAL + c)       = v0;
                    *(float2*)(out + (size_t)(r0 + 8) * N_TOTAL + c) = v1;
                }
            }
        }
    }
}

// ---------------- launch ----------------
extern "C" void kernel_launch(void* const* d_in, const int* in_sizes, int n_in,
                              void* d_out, int out_size) {
    const float* x   = (const float*)d_in[0];
    const int*   wp  = (const int*)d_in[1];
    const float* scl = (const float*)d_in[2];
    const float* bia = (const float*)d_in[3];
    float* out = (float*)d_out;

    cudaFuncSetAttribute(k_gemm, cudaFuncAttributeMaxDynamicSharedMemorySize, SMEM_BYTES);

    // fused prep: 8192 convert blocks + 22016 dequant blocks (tile-major, pre-swizzled)
    k_prep<<<30208, 256>>>(x, wp);
    // persistent GEMM, 2 CTAs/SM, bulk-TMA pipeline
    k_gemm<<<296, NTHREADS, SMEM_BYTES>>>(scl, bia, out);
}

// round 10
// speedup vs baseline: 1.0615x; 1.0043x over previous
#include <cuda_runtime.h>
#include <cuda_fp16.h>
#include <cstdint>

// ---------------- problem constants ----------------
#define M_TOTAL   4096
#define K_TOTAL   4096
#define N_TOTAL   11008

#define BM        128
#define BN        128
#define BK        64                  // fp16 per K chunk (128 B/row)
#define NKIT      (K_TOTAL / BK)      // 64
#define MT_TILES  (M_TOTAL / BM)      // 32
#define NT_TILES  (N_TOTAL / BN)      // 86
#define NTILES    (MT_TILES * NT_TILES)  // 2752
#define STAGES    3
#define NTHREADS  256

#define CHUNK_BYTES   16384                             // one (tile,kc) block, pre-swizzled
#define A_STAGE_BYTES CHUNK_BYTES
#define STAGE_BYTES   (2 * CHUNK_BYTES)                 // A + B = 32768
#define SMEM_DATA     (STAGES * STAGE_BYTES)            // 98304
#define SMEM_MBAR     SMEM_DATA                         // full[3] then empty[3]
#define SMEM_BYTES    (SMEM_DATA + 64)

// ---------------- device scratch (tile-major, pre-swizzled) ----------------
static __device__ __align__(16) __half g_xh[(size_t)M_TOTAL * K_TOTAL];   // ~34 MB
static __device__ __align__(16) __half g_w [(size_t)N_TOTAL * K_TOTAL];   // ~90 MB
static __device__ int g_ctr;

// ---------------- helpers ----------------
#define SWZ(off) ((off) ^ (((off) >> 3) & 0x70))

__device__ __forceinline__ uint32_t smem_u32(const void* p) {
    uint32_t a;
    asm("{ .reg .u64 t; cvta.to.shared.u64 t, %1; cvt.u32.u64 %0, t; }" : "=r"(a) : "l"(p));
    return a;
}

#define CP_BULK(dst_u32, src_ptr, bytes, mbar_u32) \
    asm volatile("cp.async.bulk.shared::cluster.global.mbarrier::complete_tx::bytes " \
                 "[%0], [%1], %2, [%3];" \
                 :: "r"(dst_u32), "l"(src_ptr), "r"(bytes), "r"(mbar_u32) : "memory")

#define MBARRIER_INIT(mbar, cnt) \
    asm volatile("mbarrier.init.shared.b64 [%0], %1;" \
                 :: "r"((uint32_t)(mbar)), "r"((uint32_t)(cnt)) : "memory")
#define MBARRIER_EXPECT_TX(mbar, tx) \
    asm volatile("mbarrier.arrive.expect_tx.shared.b64 _, [%0], %1;" \
                 :: "r"((uint32_t)(mbar)), "r"((uint32_t)(tx)) : "memory")
#define MBARRIER_ARRIVE(mbar) \
    asm volatile("mbarrier.arrive.shared.b64 _, [%0];" \
                 :: "r"((uint32_t)(mbar)) : "memory")

#define MBARRIER_WAIT_PARITY(mbar_smem_addr, phase_parity) do { \
    uint32_t _mbar = (uint32_t)(mbar_smem_addr); \
    uint32_t _parity = (uint32_t)(phase_parity); \
    uint32_t _done; \
    asm volatile( \
        "{\n\t.reg .pred p;\n\t" \
        "mbarrier.try_wait.parity.acquire.cta.shared::cta.b64 p, [%1], %2;\n\t" \
        "selp.b32 %0, 1, 0, p;\n\t}" \
        : "=r"(_done) : "r"(_mbar), "r"(_parity) : "memory"); \
    if (!_done) { \
        asm volatile( \
            "{\n\t.reg .pred P1;\n\t" \
            "WAIT_LOOP_%=:\n\t" \
            "mbarrier.try_wait.parity.acquire.cta.shared::cta.b64 P1, [%0], %1, 0x989680;\n\t" \
            "@P1 bra.uni WAIT_DONE_%=;\n\t" \
            "bra.uni WAIT_LOOP_%=;\n\t" \
            "WAIT_DONE_%=:\n\t}" \
            :: "r"(_mbar), "r"(_parity) : "memory"); \
    } \
} while (0)

#define LDSM_X4(r0, r1, r2, r3, addr) \
    asm volatile("ldmatrix.sync.aligned.m8n8.x4.shared.b16 {%0,%1,%2,%3}, [%4];" \
                 : "=r"(r0), "=r"(r1), "=r"(r2), "=r"(r3) : "r"(addr))

#define MMA16816(c, a, b) \
    asm volatile("mma.sync.aligned.m16n8k16.row.col.f32.f16.f16.f32 " \
                 "{%0,%1,%2,%3}, {%4,%5,%6,%7}, {%8,%9}, {%0,%1,%2,%3};" \
                 : "+f"((c)[0]), "+f"((c)[1]), "+f"((c)[2]), "+f"((c)[3]) \
                 : "r"((a)[0]), "r"((a)[1]), "r"((a)[2]), "r"((a)[3]), \
                   "r"((b)[0]), "r"((b)[1]))

// ---------------- fused prep kernel: tile-major pre-swizzled outputs ----------------
__device__ __forceinline__ uint32_t dq_pair(int v) {
    int lo = (v & 15) - 8;
    int hi = ((v >> 4) & 15) - 8;
    __half2 h = __floats2half2_rn((float)lo, (float)hi);
    return *(uint32_t*)&h;
}

__global__ void k_prep(const float* __restrict__ x, const int* __restrict__ wp) {
    if (blockIdx.x == 0 && threadIdx.x == 0) g_ctr = 0;
    if (blockIdx.x < 8192) {
        size_t i = ((size_t)blockIdx.x * blockDim.x + threadIdx.x) * 8;
        int m = (int)(i >> 12);
        int k = (int)(i & 4095);
        float4 a = *(const float4*)(x + i);
        float4 b = *(const float4*)(x + i + 4);
        __half2 h0 = __floats2half2_rn(a.x, a.y);
        __half2 h1 = __floats2half2_rn(a.z, a.w);
        __half2 h2 = __floats2half2_rn(b.x, b.y);
        __half2 h3 = __floats2half2_rn(b.z, b.w);
        uint4 o;
        o.x = *(uint32_t*)&h0; o.y = *(uint32_t*)&h1;
        o.z = *(uint32_t*)&h2; o.w = *(uint32_t*)&h3;
        int chunk = (m >> 7) * NKIT + (k >> 6);
        uint32_t off = SWZ((uint32_t)(m & 127) * 128 + (uint32_t)((k & 63) >> 3) * 16);
        *(uint4*)((char*)g_xh + ((size_t)chunk << 14) + off) = o;
    } else {
        size_t c = ((size_t)(blockIdx.x - 8192) * blockDim.x + threadIdx.x) * 4;
        int o_row = (int)(c >> 11);
        int k0 = (int)(c & 2047) * 2;
        int4 v = *(const int4*)(wp + c);
        uint4 o;
        o.x = dq_pair(v.x); o.y = dq_pair(v.y);
        o.z = dq_pair(v.z); o.w = dq_pair(v.w);
        int chunk = (o_row >> 7) * NKIT + (k0 >> 6);
        uint32_t off = SWZ((uint32_t)(o_row & 127) * 128 + (uint32_t)((k0 & 63) >> 3) * 16);
        *(uint4*)((char*)g_w + ((size_t)chunk << 14) + off) = o;
    }
}

// ---------------- persistent GEMM: full mbarrier ring, no per-iter syncthreads ----------------
__global__ __launch_bounds__(NTHREADS, 2) void k_gemm(const float* __restrict__ scale,
                                                      const float* __restrict__ bias,
                                                      float* __restrict__ out) {
    extern __shared__ __align__(1024) char smem[];
    __shared__ int s_tile;

    const int tid  = threadIdx.x;
    const int wid  = tid >> 5;
    const int lane = tid & 31;

    const int wm0 = (wid & 1) * 64;
    const int wn0 = (wid >> 1) * 32;

    const uint32_t sb = smem_u32(smem);
    const uint32_t mb_full  = sb + SMEM_MBAR;        // full[s]  at +8*s
    const uint32_t mb_empty = sb + SMEM_MBAR + 24;   // empty[s] at +8*s
    const int lrow = lane & 15;
    const int lchk = lane >> 4;

    // LDSM address algebra (row&7 == lrow&7 for all fragment rows)
    const uint32_t b0x = ((uint32_t)(lchk ^ (lrow & 1))) << 4;
    uint32_t baseA[4], baseB[2];
    #pragma unroll
    for (int mti = 0; mti < 4; ++mti)
        baseA[mti] = (uint32_t)(wm0 + mti * 16 + lrow) * 128 + b0x;
    #pragma unroll
    for (int np = 0; np < 2; ++np)
        baseB[np] = A_STAGE_BYTES + (uint32_t)(wn0 + np * 16 + lrow) * 128 + b0x;
    const uint32_t kx6 = (uint32_t)(lrow & 6);

    // init barriers + fetch first tile
    if (tid == 0) {
        #pragma unroll
        for (int s = 0; s < STAGES; ++s) {
            MBARRIER_INIT(mb_full  + 8 * s, 1);
            MBARRIER_INIT(mb_empty + 8 * s, 8);
        }
        s_tile = atomicAdd(&g_ctr, 1);
    }
    __syncthreads();
    int t_cur = s_tile;

    // pipeline cursors (uniform across threads; producer side only acted on by tid 0)
    int pstage = 0, pphase = 1;     // producer empty-wait cursor (phase 1: first pass free)
    int cstage = 0, cphase = 0;     // consumer full-wait cursor

    // prologue: produce chunks 0,1 of first tile
    if (t_cur < NTILES) {
        const char* gA0 = (const char*)g_xh + ((size_t)((t_cur % MT_TILES) * NKIT) << 14);
        const char* gB0 = (const char*)g_w  + ((size_t)((t_cur / MT_TILES) * NKIT) << 14);
        #pragma unroll
        for (int c = 0; c < 2; ++c) {
            if (tid == 0) {
                const uint32_t bar = mb_full + 8 * pstage;
                MBARRIER_EXPECT_TX(bar, STAGE_BYTES);
                CP_BULK(sb + pstage * STAGE_BYTES,                 gA0 + ((size_t)c << 14), CHUNK_BYTES, bar);
                CP_BULK(sb + pstage * STAGE_BYTES + A_STAGE_BYTES, gB0 + ((size_t)c << 14), CHUNK_BYTES, bar);
            }
            if (++pstage == STAGES) { pstage = 0; pphase ^= 1; }
        }
    }

    while (t_cur < NTILES) {
        // prefetch NEXT tile id (enables cross-tile pipeline continuity)
        if (tid == 0) s_tile = atomicAdd(&g_ctr, 1);
        __syncthreads();
        const int t_next = s_tile;

        const int mt = t_cur % MT_TILES;
        const int nt = t_cur / MT_TILES;
        const int m0 = mt * BM;
        const int n0 = nt * BN;

        const char* gA_cur = (const char*)g_xh + ((size_t)(mt * NKIT) << 14);
        const char* gB_cur = (const char*)g_w  + ((size_t)(nt * NKIT) << 14);
        const char* gA_nxt = gA_cur;  // overwritten if t_next valid
        const char* gB_nxt = gB_cur;
        if (t_next < NTILES) {
            gA_nxt = (const char*)g_xh + ((size_t)((t_next % MT_TILES) * NKIT) << 14);
            gB_nxt = (const char*)g_w  + ((size_t)((t_next / MT_TILES) * NKIT) << 14);
        }

        float acc[4][4][4];
        #pragma unroll
        for (int i = 0; i < 4; ++i)
            #pragma unroll
            for (int j = 0; j < 4; ++j)
                #pragma unroll
                for (int k = 0; k < 4; ++k) acc[i][j][k] = 0.f;

        for (int it = 0; it < NKIT; ++it) {
            // ---- producer: chunk it+2 (spills into next tile's chunks 0,1) ----
            int pc = it + 2;
            bool have;
            const char *pa, *pb;
            if (pc < NKIT) {
                have = true;
                pa = gA_cur + ((size_t)pc << 14);
                pb = gB_cur + ((size_t)pc << 14);
            } else if (t_next < NTILES) {
                have = true;
                pa = gA_nxt + ((size_t)(pc - NKIT) << 14);
                pb = gB_nxt + ((size_t)(pc - NKIT) << 14);
            } else {
                have = false; pa = pb = nullptr;
            }
            if (have) {
                if (tid == 0) {
                    MBARRIER_WAIT_PARITY(mb_empty + 8 * pstage, (uint32_t)pphase);
                    const uint32_t bar = mb_full + 8 * pstage;
                    MBARRIER_EXPECT_TX(bar, STAGE_BYTES);
                    CP_BULK(sb + pstage * STAGE_BYTES,                 pa, CHUNK_BYTES, bar);
                    CP_BULK(sb + pstage * STAGE_BYTES + A_STAGE_BYTES, pb, CHUNK_BYTES, bar);
                }
                if (++pstage == STAGES) { pstage = 0; pphase ^= 1; }
            }

            // ---- consumer: stage cstage ----
            MBARRIER_WAIT_PARITY(mb_full + 8 * cstage, (uint32_t)cphase);
            const uint32_t sA = sb + cstage * STAGE_BYTES;
            #pragma unroll
            for (int ks = 0; ks < 4; ++ks) {
                const uint32_t kbase = sA + ((((uint32_t)(2 * ks)) ^ kx6) << 4);
                uint32_t a[4][4];
                #pragma unroll
                for (int mti = 0; mti < 4; ++mti)
                    LDSM_X4(a[mti][0], a[mti][1], a[mti][2], a[mti][3],
                            kbase + baseA[mti]);
                uint32_t b[4][2];
                #pragma unroll
                for (int np = 0; np < 2; ++np) {
                    uint32_t r0, r1, r2, r3;
                    LDSM_X4(r0, r1, r2, r3, kbase + baseB[np]);
                    b[2 * np + 0][0] = r0; b[2 * np + 0][1] = r2;
                    b[2 * np + 1][0] = r1; b[2 * np + 1][1] = r3;
                }
                #pragma unroll
                for (int mti = 0; mti < 4; ++mti)
                    #pragma unroll
                    for (int nti = 0; nti < 4; ++nti)
                        MMA16816(acc[mti][nti], a[mti], b[nti]);
            }
            // release stage (per-warp arrive; release orders prior smem reads)
            if (lane == 0) MBARRIER_ARRIVE(mb_empty + 8 * cstage);
            if (++cstage == STAGES) { cstage = 0; cphase ^= 1; }
        }

        // ---------------- epilogue (overlaps next tile's TMA) ----------------
        {
            const int row_base = m0 + wm0;
            const int col_base = n0 + wn0;
            const int r_in = lane >> 2;
            const int c_in = (lane & 3) * 2;

            #pragma unroll
            for (int nti = 0; nti < 4; ++nti) {
                const int c = col_base + nti * 8 + c_in;
                const float2 sc = *(const float2*)(scale + c);
                const float2 bi = *(const float2*)(bias + c);
                #pragma unroll
                for (int mti = 0; mti < 4; ++mti) {
                    const int r0 = row_base + mti * 16 + r_in;
                    float2 v0, v1;
                    v0.x = acc[mti][nti][0] * sc.x + bi.x;
                    v0.y = acc[mti][nti][1] * sc.y + bi.y;
                    v1.x = acc[mti][nti][2] * sc.x + bi.x;
                    v1.y = acc[mti][nti][3] * sc.y + bi.y;
                    *(float2*)(out + (size_t)r0 * N_TOTAL + c)       = v0;
                    *(float2*)(out + (size_t)(r0 + 8) * N_TOTAL + c) = v1;
                }
            }
        }

        t_cur = t_next;
    }
}

// ---------------- launch ----------------
extern "C" void kernel_launch(void* const* d_in, const int* in_sizes, int n_in,
                              void* d_out, int out_size) {
    const float* x   = (const float*)d_in[0];
    const int*   wp  = (const int*)d_in[1];
    const float* scl = (const float*)d_in[2];
    const float* bia = (const float*)d_in[3];
    float* out = (float*)d_out;

    cudaFuncSetAttribute(k_gemm, cudaFuncAttributeMaxDynamicSharedMemorySize, SMEM_BYTES);

    // fused prep: tile-major, pre-swizzled
    k_prep<<<30208, 256>>>(x, wp);
    // persistent GEMM, 2 CTAs/SM, continuous mbarrier-ring pipeline
    k_gemm<<<296, NTHREADS, SMEM_BYTES>>>(scl, bia, out);
}